// round 16
// baseline (speedup 1.0000x reference)
#include <cuda_runtime.h>

#define NB   512
#define NPG  256
#define KSEL 60
#define HID  128
#define EPG  4096
#define NTOT 131072
#define ETOT 2097152
#define TLD  385
#define TLDP 388
#define XS   260   // transposed-x row stride (floats); rows k>=64 at +4 float column offset
#define HSD  132   // h row stride (floats); cols 64..127 stored at physical offset 68

#define XBUF_F 33792   // max(128*260+4, 256*132)
#define WSH_F  16384
#define CSRN_F 4096
#define SMEM_BYTES ((XBUF_F + WSH_F + CSRN_F) * 4 + EPG * 2 + 4 * 1024 + 512 + 256 + 1024)

#define NTHR 512

typedef unsigned long long u64;
typedef unsigned int u32;
struct alignas(16) u64x2 { u64 x, y; };

__device__ __forceinline__ u64 f2dup(float a) {
    u64 r; asm("mov.b64 %0, {%1, %1};" : "=l"(r) : "f"(a)); return r;
}
__device__ __forceinline__ u64 fpack(float a, float b) {
    u64 r; asm("mov.b64 %0, {%1, %2};" : "=l"(r) : "f"(a), "f"(b)); return r;
}
__device__ __forceinline__ float2 funpk(u64 v) {
    float2 f; asm("mov.b64 {%0, %1}, %2;" : "=f"(f.x), "=f"(f.y) : "l"(v)); return f;
}
__device__ __forceinline__ u64 fma2(u64 a, u64 b, u64 c) {
    u64 d; asm("fma.rn.f32x2 %0, %1, %2, %3;" : "=l"(d) : "l"(a), "l"(b), "l"(c)); return d;
}
__device__ __forceinline__ u64 mul2(u64 a, u64 b) {
    u64 d; asm("mul.rn.f32x2 %0, %1, %2;" : "=l"(d) : "l"(a), "l"(b)); return d;
}
__device__ __forceinline__ u64 add2(u64 a, u64 b) {
    u64 d; asm("add.rn.f32x2 %0, %1, %2;" : "=l"(d) : "l"(a), "l"(b)); return d;
}
__device__ __forceinline__ void cpa16(void* dst, const void* src) {
    unsigned sa = (unsigned)__cvta_generic_to_shared(dst);
    asm volatile("cp.async.ca.shared.global [%0], [%1], 16;" :: "r"(sa), "l"(src) : "memory");
}
#define CPA_COMMIT() asm volatile("cp.async.commit_group;" ::: "memory")
#define CPA_WAIT()   asm volatile("cp.async.wait_group 0;" ::: "memory")

// XLA CPU EmitFastTanh (with_fma=false): rational 13/6, clamp +-7.90531110763549805,
// passthrough |x| < 0.0004. All ops explicitly non-contracted, IEEE round-to-nearest.
__device__ __forceinline__ float xla_tanh(float x) {
    float ax = fabsf(x);
    float xc = fminf(fmaxf(x, -7.90531110763549805f), 7.90531110763549805f);
    float x2 = __fmul_rn(xc, xc);
    float p = -2.76076847742355e-16f;
    p = __fadd_rn(__fmul_rn(x2, p),  2.00018790482477e-13f);
    p = __fadd_rn(__fmul_rn(x2, p), -8.60467152213735e-11f);
    p = __fadd_rn(__fmul_rn(x2, p),  5.12229709037114e-08f);
    p = __fadd_rn(__fmul_rn(x2, p),  1.48572235717979e-05f);
    p = __fadd_rn(__fmul_rn(x2, p),  6.37261928875436e-04f);
    p = __fadd_rn(__fmul_rn(x2, p),  4.89352455891786e-03f);
    p = __fmul_rn(xc, p);
    float q = 1.19825839466702e-06f;
    q = __fadd_rn(__fmul_rn(x2, q), 1.18534705686654e-04f);
    q = __fadd_rn(__fmul_rn(x2, q), 2.26843463243900e-03f);
    q = __fadd_rn(__fmul_rn(x2, q), 4.89352518554385e-03f);
    float r = __fdiv_rn(p, q);
    return (ax < 0.0004f) ? x : r;
}

// per-node concat features [NTOT][388] (385 used, padded)
__device__ __align__(16) float g_xcat[(size_t)NTOT * TLDP];

__global__ void __launch_bounds__(NTHR, 1) dgcnn_fused(
    const float* __restrict__ z_table,
    const float* __restrict__ W0, const float* __restrict__ b0,
    const float* __restrict__ W1, const float* __restrict__ b1,
    const float* __restrict__ W2, const float* __restrict__ b2,
    const float* __restrict__ W3, const float* __restrict__ b3,
    const float* __restrict__ c1w, const float* __restrict__ c1b,
    const float* __restrict__ c2w, const float* __restrict__ c2b,
    const float* __restrict__ l1w, const float* __restrict__ l1b,
    const float* __restrict__ l2w, const float* __restrict__ l2b,
    const float* __restrict__ ew,  const int* __restrict__ zz,
    const int* __restrict__ eidx,
    float* __restrict__ out)
{
    extern __shared__ float sm[];
    float* xbuf = sm;                                   // 33792 f
    float* Wsh  = xbuf + XBUF_F;                        // 16384 f
    float* csrn = Wsh + WSH_F;                          // 4096 f
    unsigned short* csrs = (unsigned short*)(csrn + CSRN_F); // 4096 u16
    int*   row_end = (int*)(csrs + EPG);                // 256
    int*   cursor  = row_end + NPG;                     // 256 (reused as h3)
    float* dinv    = (float*)(cursor + NPG);            // 256
    float* x3      = dinv + NPG;                        // 256 (bias ping buffer / scores)
    float* bsh     = x3 + NPG;                          // 128 (bias pong buffer / W3)
    int*   sel     = (int*)(bsh + HID);                 // 64
    int*   nodemap = sel + 64;                          // 256 (degree-balanced order)

    unsigned short* pe    = csrs;                       // staging (s<<8|d) -- csrs idle til norms
    u32*            spack = (u32*)csrn;                 // staging (e<<16|d<<8|s)

    const int g     = blockIdx.x;
    const int tid   = threadIdx.x;
    const int base  = g * NPG;
    const int ebase = g * EPG;

    // ---------------- W0/b0 prefetch: overlaps the entire build phase ----------------
    for (int i = tid * 4; i < HID * HID; i += NTHR * 4)
        cpa16(&Wsh[i], &W0[i]);
    if (tid < 32) cpa16(&bsh[tid * 4], &b0[tid * 4]);
    CPA_COMMIT();

    // ---------------- stage edges + per-dst counts (int atomics: deterministic) ---------
    if (tid < NPG) row_end[tid] = 0;
    __syncthreads();
    for (int e = tid; e < EPG; e += NTHR) {
        int s = eidx[ebase + e] - base;
        int d = eidx[ETOT + ebase + e] - base;
        pe[e] = (unsigned short)((s << 8) | d);
        atomicAdd(&row_end[d], 1);
    }
    __syncthreads();
    // inclusive scan of 256 counts: warp shuffles + warp-total fixup (integer-exact)
    if (tid < NPG) {
        int v = row_end[tid];
        #pragma unroll
        for (int s = 1; s < 32; s <<= 1) {
            int u = __shfl_up_sync(0xffffffffu, v, s);
            if ((tid & 31) >= s) v += u;
        }
        if ((tid & 31) == 31) sel[tid >> 5] = v;   // 8 warp totals
        cursor[tid] = v;                            // warp-local inclusive stash
    }
    __syncthreads();
    if (tid < NPG) {
        int w = tid >> 5, off = 0;
        #pragma unroll
        for (int j = 0; j < 7; ++j) off += (j < w) ? sel[j] : 0;
        row_end[tid] = cursor[tid] + off;
    }
    __syncthreads();
    if (tid < NPG) cursor[tid] = (tid == 0) ? 0 : row_end[tid - 1];
    __syncthreads();

    // ---------------- warp 0: deterministic e-ascending CSR scatter; others: x0 gather ---
    if (tid < 32) {
        for (int it = 0; it < EPG / 32; ++it) {
            int e = it * 32 + tid;
            unsigned v = pe[e];
            int d = v & 255, s = v >> 8;
            unsigned mask = __match_any_sync(0xffffffffu, d);
            int leader = __ffs(mask) - 1;
            int rank = __popc(mask & ((1u << tid) - 1u));
            int old = 0;
            if (tid == leader) old = atomicAdd(&cursor[d], __popc(mask));
            old = __shfl_sync(0xffffffffu, old, leader);
            spack[old + rank] = ((u32)e << 16) | ((u32)d << 8) | (u32)s;
        }
    } else {
        for (int idx = tid - 32; idx < NPG * HID; idx += (NTHR - 32)) {
            int n = idx >> 7, k = idx & 127;
            xbuf[k * XS + ((k >= 64) ? 4 : 0) + n] = z_table[zz[base + n] * HID + k];
        }
    }
    __syncthreads();

    // ---------------- deg: edges in e-order, self-loop LAST; dinv = 1/sqrt --------------
    if (tid < NPG) {
        int s0 = (tid == 0) ? 0 : row_end[tid - 1];
        int s1 = row_end[tid];
        float deg = 0.0f;
        for (int i = s0; i < s1; ++i)
            deg = __fadd_rn(deg, ew[ebase + (spack[i] >> 16)]);
        deg = __fadd_rn(deg, 1.0f);
        dinv[tid] = __fdiv_rn(1.0f, __fsqrt_rn(deg));
    }
    __syncthreads();
    // ---------------- norms: (dinv[s]*ew)*dinv[d]  (pe dead after scatter; csrs reused) --
    for (int i = tid; i < EPG; i += NTHR) {
        u32 p = spack[i];
        int e = p >> 16, d = (p >> 8) & 255, s = p & 255;
        float nr = __fmul_rn(__fmul_rn(dinv[s], ew[ebase + e]), dinv[d]);
        csrs[i] = (unsigned short)s;
        csrn[i] = nr;
    }
    // ---------------- degree-balanced node order (deterministic): rank by (deg desc, id) --
    if (tid < NPG) {
        int b0i = (tid == 0) ? 0 : row_end[tid - 1];
        int myc = row_end[tid] - b0i;
        int rank = 0;
        for (int j = 0; j < NPG; ++j) {
            int bj = (j == 0) ? 0 : row_end[j - 1];
            int cj = row_end[j] - bj;
            rank += (cj > myc) || (cj == myc && j < tid);
        }
        nodemap[rank] = tid;
    }
    CPA_WAIT();          // W0/b0 landed (overlapped with build)
    __syncthreads();

    float* xcat = g_xcat + (size_t)base * TLDP;

    // GEMM mapping: warp covers 32 nodes x 64 cols (wavefront-minimal).
    const int lane = tid & 31;
    const int wrp  = tid >> 5;
    const int n0 = ((wrp & 7) * 4 + (lane >> 3)) * 8;   // 32 node-groups
    const int c0 = ((wrp >> 3) * 8 + (lane & 7)) * 8;   // 16 col-strips (logical)
    const int c0p = c0 + (c0 >= 64 ? 4 : 0);            // physical col in H layout
    const int ch  = (tid & 1) * 64;                     // agg: 64-col half (logical)
    const int chp = ch ? 68 : 0;                        // physical half base in H layout
    const int chx = ch ? 4 : 0;                         // x^T column offset for rows >= 64

    // bias ping-pong: L0->bsh, L1->x3, L2->bsh (prefetched during prior agg)
    // ---------------- layers 0..2 : 128 -> 128 ----------------
    for (int layer = 0; layer < 3; ++layer) {
        const float* bcur = (layer == 1) ? x3 : bsh;

        u64 acc[4][8];
        #pragma unroll
        for (int p = 0; p < 4; ++p)
            #pragma unroll
            for (int j = 0; j < 8; ++j) acc[p][j] = 0ULL;

        // Manually software-pipelined, 2-deep, rolling pointers. x^T rows >= 64 sit at a
        // +4-float column offset; the single seam is handled by predicated bumps at k==62.
        // Semantics identical to sequential-k FMA chain (Eigen gebp): only load timing moves.
        {
            const float* xpa = &xbuf[n0];          // row k
            const float* wpa = &Wsh[c0];
            const float* xpb = xpa + XS;           // row k+1
            const float* wpb = wpa + HID;
            u64x2 aA0 = *(const u64x2*)xpa;
            u64x2 aA1 = *(const u64x2*)(xpa + 4);
            float4 wA0 = *(const float4*)wpa;
            float4 wA1 = *(const float4*)(wpa + 4);
            #pragma unroll 1
            for (int k = 0; k < HID; k += 2) {
                u64x2 aB0 = *(const u64x2*)xpb;                // row k+1
                u64x2 aB1 = *(const u64x2*)(xpb + 4);
                float4 wB0 = *(const float4*)wpb;
                float4 wB1 = *(const float4*)(wpb + 4);
                xpb += 2 * XS; wpb += 2 * HID;                 // -> row k+3
                if (k == 62) xpb += 4;                         // row 65+: offset half
                {
                    u64 ap[4] = { aA0.x, aA0.y, aA1.x, aA1.y };
                    u64 wd[8] = { f2dup(wA0.x), f2dup(wA0.y), f2dup(wA0.z), f2dup(wA0.w),
                                  f2dup(wA1.x), f2dup(wA1.y), f2dup(wA1.z), f2dup(wA1.w) };
                    #pragma unroll
                    for (int p = 0; p < 4; ++p)
                        #pragma unroll
                        for (int j = 0; j < 8; ++j)
                            acc[p][j] = fma2(ap[p], wd[j], acc[p][j]);
                }
                xpa += 2 * XS; wpa += 2 * HID;                 // -> row k+2
                if (k == 62) xpa += 4;                         // row 64+: offset half
                aA0 = *(const u64x2*)xpa;                      // last iter: in-bounds garbage
                aA1 = *(const u64x2*)(xpa + 4);
                wA0 = *(const float4*)wpa;
                wA1 = *(const float4*)(wpa + 4);
                {
                    u64 ap[4] = { aB0.x, aB0.y, aB1.x, aB1.y };
                    u64 wd[8] = { f2dup(wB0.x), f2dup(wB0.y), f2dup(wB0.z), f2dup(wB0.w),
                                  f2dup(wB1.x), f2dup(wB1.y), f2dup(wB1.z), f2dup(wB1.w) };
                    #pragma unroll
                    for (int p = 0; p < 4; ++p)
                        #pragma unroll
                        for (int j = 0; j < 8; ++j)
                            acc[p][j] = fma2(ap[p], wd[j], acc[p][j]);
                }
            }
        }
        __syncthreads();
        // stash h row-major (upper 64 logical cols at physical offset 68)
        #pragma unroll
        for (int p = 0; p < 4; ++p) {
            float lo[8], hi[8];
            #pragma unroll
            for (int j = 0; j < 8; ++j) {
                float2 t = funpk(acc[p][j]);
                lo[j] = t.x; hi[j] = t.y;
            }
            int ra = n0 + 2 * p, rb = ra + 1;
            *(float4*)&xbuf[ra * HSD + c0p]     = make_float4(lo[0], lo[1], lo[2], lo[3]);
            *(float4*)&xbuf[ra * HSD + c0p + 4] = make_float4(lo[4], lo[5], lo[6], lo[7]);
            *(float4*)&xbuf[rb * HSD + c0p]     = make_float4(hi[0], hi[1], hi[2], hi[3]);
            *(float4*)&xbuf[rb * HSD + c0p + 4] = make_float4(hi[4], hi[5], hi[6], hi[7]);
        }
        __syncthreads();

        // prefetch next layer's W (+bias into the idle ping-pong buffer) during agg
        if (layer < 2) {
            const float* Wn = (layer == 0) ? W1 : W2;
            const float* bn = (layer == 0) ? b1 : b2;
            float* bdst = (layer == 0) ? x3 : bsh;
            for (int i = tid * 4; i < HID * HID; i += NTHR * 4)
                cpa16(&Wsh[i], &Wn[i]);
            if (tid < 32) cpa16(&bdst[tid * 4], &bn[tid * 4]);
            CPA_COMMIT();
        }

        // aggregation (segment_sum semantics): edges e-order (mul,add), self LAST, +bias, tanh
        // thread slot -> node via degree-balanced nodemap; (s,w) prefetched (branchless clamp)
        u64 r2[32];
        {
            const int node = nodemap[tid >> 1];
            #pragma unroll
            for (int q = 0; q < 32; ++q) r2[q] = 0ULL;
            int s0 = (node == 0) ? 0 : row_end[node - 1];
            int s1 = row_end[node];
            int s_cur = 0; float w_cur = 0.0f;
            if (s0 < s1) { s_cur = csrs[s0]; w_cur = csrn[s0]; }
            for (int ii = s0; ii < s1; ++ii) {
                int nxt = (ii + 1 < s1) ? (ii + 1) : ii;   // branchless clamp
                int s_nxt = csrs[nxt];
                float w_nxt = csrn[nxt];
                u64 wd = f2dup(w_cur);
                const u64x2* sp = (const u64x2*)&xbuf[s_cur * HSD + chp];
                #pragma unroll
                for (int q = 0; q < 16; ++q) {
                    u64x2 v = sp[q];
                    r2[2 * q]     = add2(r2[2 * q],     mul2(v.x, wd));
                    r2[2 * q + 1] = add2(r2[2 * q + 1], mul2(v.y, wd));
                }
                s_cur = s_nxt; w_cur = w_nxt;
            }
            u64 snd = f2dup(__fmul_rn(dinv[node], dinv[node]));
            const u64x2* hp = (const u64x2*)&xbuf[node * HSD + chp];
            #pragma unroll
            for (int q = 0; q < 16; ++q) {
                u64x2 v = hp[q];
                r2[2 * q]     = add2(r2[2 * q],     mul2(v.x, snd));
                r2[2 * q + 1] = add2(r2[2 * q + 1], mul2(v.y, snd));
            }
            #pragma unroll
            for (int q = 0; q < 32; ++q) {
                float2 t = funpk(r2[q]);
                t.x = xla_tanh(__fadd_rn(t.x, bcur[ch + 2 * q]));
                t.y = xla_tanh(__fadd_rn(t.y, bcur[ch + 2 * q + 1]));
                r2[q] = fpack(t.x, t.y);
            }
            float* xr = &xcat[(size_t)node * TLDP + layer * HID + ch];
            #pragma unroll
            for (int q = 0; q < 32; q += 2) {
                u64x2 v; v.x = r2[q]; v.y = r2[q + 1];
                *(u64x2*)&xr[2 * q] = v;
            }
            __syncthreads();
            // x^T writeback: rows ch+2q (ch=64 half at +4 col offset -> pair lanes differ banks)
            #pragma unroll
            for (int q = 0; q < 32; ++q) {
                float2 t = funpk(r2[q]);
                xbuf[(ch + 2 * q) * XS + chx + node]     = t.x;
                xbuf[(ch + 2 * q + 1) * XS + chx + node] = t.y;
            }
        }
        if (layer < 2) CPA_WAIT();
        __syncthreads();
    }

    // ---------------- layer 3 : 128 -> 1 ----------------
    // XLA:CPU kTiledLlvmIrGemv semantics: 4-lane accumulators (lane = k mod 4,
    // ascending chunks, fused FMA), then shuffle-halving reduce (a0+a2)+(a1+a3).
    if (tid < HID) bsh[tid] = W3[tid];
    __syncthreads();
    float* h3 = (float*)cursor;
    if (tid < NPG) {
        float a0 = 0.0f, a1 = 0.0f, a2 = 0.0f, a3 = 0.0f;
        for (int m = 0; m < 64; m += 4) {
            a0 = __fmaf_rn(xbuf[(m + 0) * XS + tid], bsh[m + 0], a0);
            a1 = __fmaf_rn(xbuf[(m + 1) * XS + tid], bsh[m + 1], a1);
            a2 = __fmaf_rn(xbuf[(m + 2) * XS + tid], bsh[m + 2], a2);
            a3 = __fmaf_rn(xbuf[(m + 3) * XS + tid], bsh[m + 3], a3);
        }
        for (int m = 64; m < HID; m += 4) {
            a0 = __fmaf_rn(xbuf[(m + 0) * XS + 4 + tid], bsh[m + 0], a0);
            a1 = __fmaf_rn(xbuf[(m + 1) * XS + 4 + tid], bsh[m + 1], a1);
            a2 = __fmaf_rn(xbuf[(m + 2) * XS + 4 + tid], bsh[m + 2], a2);
            a3 = __fmaf_rn(xbuf[(m + 3) * XS + 4 + tid], bsh[m + 3], a3);
        }
        h3[tid] = __fadd_rn(__fadd_rn(a0, a2), __fadd_rn(a1, a3));
    }
    __syncthreads();
    if (tid < NPG) {
        float acc = 0.0f;
        int s0 = (tid == 0) ? 0 : row_end[tid - 1];
        int s1 = row_end[tid];
        for (int ii = s0; ii < s1; ++ii)
            acc = __fadd_rn(acc, __fmul_rn(h3[csrs[ii]], csrn[ii]));
        acc = __fadd_rn(acc, __fmul_rn(h3[tid], __fmul_rn(dinv[tid], dinv[tid])));
        acc = __fadd_rn(acc, b3[0]);
        float v = xla_tanh(acc);
        x3[tid] = v;
        xcat[(size_t)tid * TLDP + 384] = v;
    }
    __syncthreads();

    // ---------------- stable descending top-K via rank ----------------
    if (tid < NPG) {
        float v = x3[tid];
        int rank = 0;
        for (int j = 0; j < NPG; ++j) {
            float u = x3[j];
            rank += (u > v) || (u == v && j < tid);
        }
        if (rank < KSEL) sel[rank] = tid;
    }
    __syncthreads();

    // ---------------- head ----------------
    for (int idx = tid; idx < KSEL * TLDP; idx += NTHR) {
        int k = idx / TLDP, t = idx - k * TLDP;
        xbuf[idx] = (t < TLD) ? xcat[(size_t)sel[k] * TLDP + t] : 0.0f;
    }
    for (int idx = tid; idx < 16 * TLD; idx += NTHR) {
        int oc = idx / TLD, t = idx - oc * TLD;
        Wsh[oc * TLDP + t] = c1w[idx];
    }
    float* c2wsh = Wsh + 16 * TLDP;
    for (int idx = tid; idx < 32 * 16 * 5; idx += NTHR) c2wsh[idx] = c2w[idx];
    if (tid < 16) x3[tid] = c1b[tid];
    if (tid < 32) x3[16 + tid] = c2b[tid];
    __syncthreads();

    float* out1 = csrn;          // [16][60]
    float* pl   = csrn + 960;    // [16][30]
    float* v2   = csrn + 1440;   // [832]
    float* y1   = csrn + 2272;   // [128]
    float* part = csrn + 2400;   // [512]

    for (int task = tid; task < 16 * KSEL; task += NTHR) {
        int oc = task / KSEL, k = task - oc * KSEL;
        const float* pr = &xbuf[k * TLDP];
        const float* wr = &Wsh[oc * TLDP];
        float acc = x3[oc];
        for (int t = 0; t < 384; t += 4) {
            float4 pv = *(const float4*)&pr[t];
            float4 wv = *(const float4*)&wr[t];
            acc += pv.x * wv.x + pv.y * wv.y + pv.z * wv.z + pv.w * wv.w;
        }
        acc += pr[384] * wr[384];
        out1[oc * KSEL + k] = fmaxf(acc, 0.0f);
    }
    __syncthreads();
    for (int task = tid; task < 16 * 30; task += NTHR) {
        int ic = task / 30, j = task - ic * 30;
        pl[ic * 30 + j] = fmaxf(out1[ic * 60 + 2 * j], out1[ic * 60 + 2 * j + 1]);
    }
    __syncthreads();
    for (int task = tid; task < 32 * 26; task += NTHR) {
        int oc = task / 26, j = task - oc * 26;
        float acc = x3[16 + oc];
        #pragma unroll
        for (int ic = 0; ic < 16; ++ic)
            #pragma unroll
            for (int p = 0; p < 5; ++p)
                acc += c2wsh[oc * 80 + ic * 5 + p] * pl[ic * 30 + j + p];
        v2[oc * 26 + j] = fmaxf(acc, 0.0f);
    }
    __syncthreads();
    {
        int o = tid & 127, pt = tid >> 7;
        float acc = 0.0f;
        for (int i = pt * 208; i < pt * 208 + 208; ++i)
            acc += v2[i] * l1w[i * HID + o];
        part[tid] = acc;
    }
    __syncthreads();
    if (tid < HID) {
        float y = part[tid] + part[tid + 128] + part[tid + 256] + part[tid + 384] + l1b[tid];
        y1[tid] = fmaxf(y, 0.0f);
    }
    __syncthreads();
    if (tid < HID) part[tid] = y1[tid] * l2w[tid];
    __syncthreads();
    if (tid == 0) {
        float s = 0.0f;
        for (int i = 0; i < HID; ++i) s += part[i];
        out[g] = s + l2b[0];
    }
}

extern "C" void kernel_launch(void* const* d_in, const int* in_sizes, int n_in,
                              void* d_out, int out_size) {
    (void)in_sizes; (void)n_in; (void)out_size;
    cudaFuncSetAttribute(dgcnn_fused, cudaFuncAttributeMaxDynamicSharedMemorySize, SMEM_BYTES);
    dgcnn_fused<<<NB, NTHR, SMEM_BYTES>>>(
        (const float*)d_in[0],  (const float*)d_in[1],  (const float*)d_in[2],
        (const float*)d_in[3],  (const float*)d_in[4],  (const float*)d_in[5],
        (const float*)d_in[6],  (const float*)d_in[7],  (const float*)d_in[8],
        (const float*)d_in[9],  (const float*)d_in[10], (const float*)d_in[11],
        (const float*)d_in[12], (const float*)d_in[13], (const float*)d_in[14],
        (const float*)d_in[15], (const float*)d_in[16], (const float*)d_in[17],
        (const int*)d_in[18],   (const int*)d_in[19],
        (float*)d_out);
}

// round 17
// speedup vs baseline: 1.0086x; 1.0086x over previous
#include <cuda_runtime.h>

#define NB   512
#define NPG  256
#define KSEL 60
#define HID  128
#define EPG  4096
#define NTOT 131072
#define ETOT 2097152
#define TLD  385
#define TLDP 388
#define XS   260   // transposed-x row stride (floats); rows k>=64 at +4 float column offset
#define HSD  132   // h row stride (floats); cols 64..127 stored at physical offset 68

#define XBUF_F 33792   // max(128*260+4, 256*132)
#define WSH_F  16384
#define CSRN_F 4096
#define SMEM_BYTES ((XBUF_F + WSH_F + CSRN_F) * 4 + EPG * 2 + 4 * 1024 + 512 + 256 + 1024)

#define NTHR 512

// head bias stash inside Wsh (free tail after c1w pad + c2w)
#define HB_C1B (16 * TLDP + 2560)      // 8768
#define HB_C2B (HB_C1B + 16)           // 8784

typedef unsigned long long u64;
typedef unsigned int u32;
struct alignas(16) u64x2 { u64 x, y; };

__device__ __forceinline__ u64 f2dup(float a) {
    u64 r; asm("mov.b64 %0, {%1, %1};" : "=l"(r) : "f"(a)); return r;
}
__device__ __forceinline__ u64 fpack(float a, float b) {
    u64 r; asm("mov.b64 %0, {%1, %2};" : "=l"(r) : "f"(a), "f"(b)); return r;
}
__device__ __forceinline__ float2 funpk(u64 v) {
    float2 f; asm("mov.b64 {%0, %1}, %2;" : "=f"(f.x), "=f"(f.y) : "l"(v)); return f;
}
__device__ __forceinline__ u64 fma2(u64 a, u64 b, u64 c) {
    u64 d; asm("fma.rn.f32x2 %0, %1, %2, %3;" : "=l"(d) : "l"(a), "l"(b), "l"(c)); return d;
}
__device__ __forceinline__ u64 mul2(u64 a, u64 b) {
    u64 d; asm("mul.rn.f32x2 %0, %1, %2;" : "=l"(d) : "l"(a), "l"(b)); return d;
}
__device__ __forceinline__ u64 add2(u64 a, u64 b) {
    u64 d; asm("add.rn.f32x2 %0, %1, %2;" : "=l"(d) : "l"(a), "l"(b)); return d;
}
__device__ __forceinline__ void cpa16(void* dst, const void* src) {
    unsigned sa = (unsigned)__cvta_generic_to_shared(dst);
    asm volatile("cp.async.ca.shared.global [%0], [%1], 16;" :: "r"(sa), "l"(src) : "memory");
}
__device__ __forceinline__ void cpa4(void* dst, const void* src) {
    unsigned sa = (unsigned)__cvta_generic_to_shared(dst);
    asm volatile("cp.async.ca.shared.global [%0], [%1], 4;" :: "r"(sa), "l"(src) : "memory");
}
#define CPA_COMMIT() asm volatile("cp.async.commit_group;" ::: "memory")
#define CPA_WAIT()   asm volatile("cp.async.wait_group 0;" ::: "memory")

// XLA CPU EmitFastTanh (with_fma=false): rational 13/6, clamp +-7.90531110763549805,
// passthrough |x| < 0.0004. All ops explicitly non-contracted, IEEE round-to-nearest.
__device__ __forceinline__ float xla_tanh(float x) {
    float ax = fabsf(x);
    float xc = fminf(fmaxf(x, -7.90531110763549805f), 7.90531110763549805f);
    float x2 = __fmul_rn(xc, xc);
    float p = -2.76076847742355e-16f;
    p = __fadd_rn(__fmul_rn(x2, p),  2.00018790482477e-13f);
    p = __fadd_rn(__fmul_rn(x2, p), -8.60467152213735e-11f);
    p = __fadd_rn(__fmul_rn(x2, p),  5.12229709037114e-08f);
    p = __fadd_rn(__fmul_rn(x2, p),  1.48572235717979e-05f);
    p = __fadd_rn(__fmul_rn(x2, p),  6.37261928875436e-04f);
    p = __fadd_rn(__fmul_rn(x2, p),  4.89352455891786e-03f);
    p = __fmul_rn(xc, p);
    float q = 1.19825839466702e-06f;
    q = __fadd_rn(__fmul_rn(x2, q), 1.18534705686654e-04f);
    q = __fadd_rn(__fmul_rn(x2, q), 2.26843463243900e-03f);
    q = __fadd_rn(__fmul_rn(x2, q), 4.89352518554385e-03f);
    float r = __fdiv_rn(p, q);
    return (ax < 0.0004f) ? x : r;
}

// per-node concat features [NTOT][388] (385 used, padded)
__device__ __align__(16) float g_xcat[(size_t)NTOT * TLDP];

__global__ void __launch_bounds__(NTHR, 1) dgcnn_fused(
    const float* __restrict__ z_table,
    const float* __restrict__ W0, const float* __restrict__ b0,
    const float* __restrict__ W1, const float* __restrict__ b1,
    const float* __restrict__ W2, const float* __restrict__ b2,
    const float* __restrict__ W3, const float* __restrict__ b3,
    const float* __restrict__ c1w, const float* __restrict__ c1b,
    const float* __restrict__ c2w, const float* __restrict__ c2b,
    const float* __restrict__ l1w, const float* __restrict__ l1b,
    const float* __restrict__ l2w, const float* __restrict__ l2b,
    const float* __restrict__ ew,  const int* __restrict__ zz,
    const int* __restrict__ eidx,
    float* __restrict__ out)
{
    extern __shared__ float sm[];
    float* xbuf = sm;                                   // 33792 f
    float* Wsh  = xbuf + XBUF_F;                        // 16384 f
    float* csrn = Wsh + WSH_F;                          // 4096 f
    unsigned short* csrs = (unsigned short*)(csrn + CSRN_F); // 4096 u16
    int*   row_end = (int*)(csrs + EPG);                // 256
    int*   cursor  = row_end + NPG;                     // 256 (reused as h3)
    float* dinv    = (float*)(cursor + NPG);            // 256
    float* x3      = dinv + NPG;                        // 256 (bias ping buffer / scores)
    float* bsh     = x3 + NPG;                          // 128 (bias pong buffer / W3)
    int*   sel     = (int*)(bsh + HID);                 // 64
    int*   nodemap = sel + 64;                          // 256 (degree-balanced order)

    unsigned short* pe    = csrs;                       // staging (s<<8|d) -- csrs idle til norms
    u32*            spack = (u32*)csrn;                 // staging (e<<16|d<<8|s)

    const int g     = blockIdx.x;
    const int tid   = threadIdx.x;
    const int base  = g * NPG;
    const int ebase = g * EPG;

    // ---------------- W0/b0 prefetch: overlaps the entire build phase ----------------
    for (int i = tid * 4; i < HID * HID; i += NTHR * 4)
        cpa16(&Wsh[i], &W0[i]);
    if (tid < 32) cpa16(&bsh[tid * 4], &b0[tid * 4]);
    CPA_COMMIT();

    // ---------------- stage edges + per-dst counts (int atomics: deterministic) ---------
    if (tid < NPG) row_end[tid] = 0;
    __syncthreads();
    for (int e = tid; e < EPG; e += NTHR) {
        int s = eidx[ebase + e] - base;
        int d = eidx[ETOT + ebase + e] - base;
        pe[e] = (unsigned short)((s << 8) | d);
        atomicAdd(&row_end[d], 1);
    }
    __syncthreads();
    // inclusive scan of 256 counts: warp shuffles + warp-total fixup (integer-exact)
    if (tid < NPG) {
        int v = row_end[tid];
        #pragma unroll
        for (int s = 1; s < 32; s <<= 1) {
            int u = __shfl_up_sync(0xffffffffu, v, s);
            if ((tid & 31) >= s) v += u;
        }
        if ((tid & 31) == 31) sel[tid >> 5] = v;   // 8 warp totals
        cursor[tid] = v;                            // warp-local inclusive stash
    }
    __syncthreads();
    if (tid < NPG) {
        int w = tid >> 5, off = 0;
        #pragma unroll
        for (int j = 0; j < 7; ++j) off += (j < w) ? sel[j] : 0;
        row_end[tid] = cursor[tid] + off;
    }
    __syncthreads();
    if (tid < NPG) cursor[tid] = (tid == 0) ? 0 : row_end[tid - 1];
    __syncthreads();

    // ---------------- warp 0: deterministic e-ascending CSR scatter; others: x0 gather ---
    if (tid < 32) {
        for (int it = 0; it < EPG / 32; ++it) {
            int e = it * 32 + tid;
            unsigned v = pe[e];
            int d = v & 255, s = v >> 8;
            unsigned mask = __match_any_sync(0xffffffffu, d);
            int leader = __ffs(mask) - 1;
            int rank = __popc(mask & ((1u << tid) - 1u));
            int old = 0;
            if (tid == leader) old = atomicAdd(&cursor[d], __popc(mask));
            old = __shfl_sync(0xffffffffu, old, leader);
            spack[old + rank] = ((u32)e << 16) | ((u32)d << 8) | (u32)s;
        }
    } else {
        for (int idx = tid - 32; idx < NPG * HID; idx += (NTHR - 32)) {
            int n = idx >> 7, k = idx & 127;
            xbuf[k * XS + ((k >= 64) ? 4 : 0) + n] = z_table[zz[base + n] * HID + k];
        }
    }
    __syncthreads();

    // ---------------- deg: edges in e-order, self-loop LAST; dinv = 1/sqrt --------------
    // unroll-4 batches the independent LDGs; add order unchanged (bit-exact)
    if (tid < NPG) {
        int s0 = (tid == 0) ? 0 : row_end[tid - 1];
        int s1 = row_end[tid];
        float deg = 0.0f;
        int i = s0;
        for (; i + 4 <= s1; i += 4) {
            float w0v = ew[ebase + (spack[i]     >> 16)];
            float w1v = ew[ebase + (spack[i + 1] >> 16)];
            float w2v = ew[ebase + (spack[i + 2] >> 16)];
            float w3v = ew[ebase + (spack[i + 3] >> 16)];
            deg = __fadd_rn(deg, w0v);
            deg = __fadd_rn(deg, w1v);
            deg = __fadd_rn(deg, w2v);
            deg = __fadd_rn(deg, w3v);
        }
        for (; i < s1; ++i)
            deg = __fadd_rn(deg, ew[ebase + (spack[i] >> 16)]);
        deg = __fadd_rn(deg, 1.0f);
        dinv[tid] = __fdiv_rn(1.0f, __fsqrt_rn(deg));
    }
    __syncthreads();
    // ---------------- norms: (dinv[s]*ew)*dinv[d]  (pe dead after scatter; csrs reused) --
    for (int i = tid; i < EPG; i += NTHR) {
        u32 p = spack[i];
        int e = p >> 16, d = (p >> 8) & 255, s = p & 255;
        float nr = __fmul_rn(__fmul_rn(dinv[s], ew[ebase + e]), dinv[d]);
        csrs[i] = (unsigned short)s;
        csrn[i] = nr;
    }
    // ---------------- degree-balanced node order: rank by (deg desc, id) ----------------
    // 2 threads per node, each counts half the range; integer-exact shfl_xor combine
    {
        int node = tid >> 1, ht = tid & 1;
        int bn = (node == 0) ? 0 : row_end[node - 1];
        int myc = row_end[node] - bn;
        int part = 0;
        for (int j = ht * 128; j < ht * 128 + 128; ++j) {
            int bj = (j == 0) ? 0 : row_end[j - 1];
            int cj = row_end[j] - bj;
            part += (cj > myc) || (cj == myc && j < node);
        }
        part += __shfl_xor_sync(0xffffffffu, part, 1);
        if (ht == 0) nodemap[part] = node;
    }
    CPA_WAIT();          // W0/b0 landed (overlapped with build)
    __syncthreads();

    float* xcat = g_xcat + (size_t)base * TLDP;

    // GEMM mapping: warp covers 32 nodes x 64 cols (wavefront-minimal).
    const int lane = tid & 31;
    const int wrp  = tid >> 5;
    const int n0 = ((wrp & 7) * 4 + (lane >> 3)) * 8;   // 32 node-groups
    const int c0 = ((wrp >> 3) * 8 + (lane & 7)) * 8;   // 16 col-strips (logical)
    const int c0p = c0 + (c0 >= 64 ? 4 : 0);            // physical col in H layout
    const int ch  = (tid & 1) * 64;                     // agg: 64-col half (logical)
    const int chp = ch ? 68 : 0;                        // physical half base in H layout
    const int chx = ch ? 4 : 0;                         // x^T column offset for rows >= 64

    // bias ping-pong: L0->bsh, L1->x3, L2->bsh (prefetched during prior agg)
    // ---------------- layers 0..2 : 128 -> 128 ----------------
    for (int layer = 0; layer < 3; ++layer) {
        const float* bcur = (layer == 1) ? x3 : bsh;

        u64 acc[4][8];
        #pragma unroll
        for (int p = 0; p < 4; ++p)
            #pragma unroll
            for (int j = 0; j < 8; ++j) acc[p][j] = 0ULL;

        // Manually software-pipelined, 2-deep, rolling pointers. x^T rows >= 64 sit at a
        // +4-float column offset; the single seam is handled by predicated bumps at k==62.
        // Semantics identical to sequential-k FMA chain (Eigen gebp): only load timing moves.
        {
            const float* xpa = &xbuf[n0];          // row k
            const float* wpa = &Wsh[c0];
            const float* xpb = xpa + XS;           // row k+1
            const float* wpb = wpa + HID;
            u64x2 aA0 = *(const u64x2*)xpa;
            u64x2 aA1 = *(const u64x2*)(xpa + 4);
            float4 wA0 = *(const float4*)wpa;
            float4 wA1 = *(const float4*)(wpa + 4);
            #pragma unroll 1
            for (int k = 0; k < HID; k += 2) {
                u64x2 aB0 = *(const u64x2*)xpb;                // row k+1
                u64x2 aB1 = *(const u64x2*)(xpb + 4);
                float4 wB0 = *(const float4*)wpb;
                float4 wB1 = *(const float4*)(wpb + 4);
                xpb += 2 * XS; wpb += 2 * HID;                 // -> row k+3
                if (k == 62) xpb += 4;                         // row 65+: offset half
                {
                    u64 ap[4] = { aA0.x, aA0.y, aA1.x, aA1.y };
                    u64 wd[8] = { f2dup(wA0.x), f2dup(wA0.y), f2dup(wA0.z), f2dup(wA0.w),
                                  f2dup(wA1.x), f2dup(wA1.y), f2dup(wA1.z), f2dup(wA1.w) };
                    #pragma unroll
                    for (int p = 0; p < 4; ++p)
                        #pragma unroll
                        for (int j = 0; j < 8; ++j)
                            acc[p][j] = fma2(ap[p], wd[j], acc[p][j]);
                }
                xpa += 2 * XS; wpa += 2 * HID;                 // -> row k+2
                if (k == 62) xpa += 4;                         // row 64+: offset half
                aA0 = *(const u64x2*)xpa;                      // last iter: in-bounds garbage
                aA1 = *(const u64x2*)(xpa + 4);
                wA0 = *(const float4*)wpa;
                wA1 = *(const float4*)(wpa + 4);
                {
                    u64 ap[4] = { aB0.x, aB0.y, aB1.x, aB1.y };
                    u64 wd[8] = { f2dup(wB0.x), f2dup(wB0.y), f2dup(wB0.z), f2dup(wB0.w),
                                  f2dup(wB1.x), f2dup(wB1.y), f2dup(wB1.z), f2dup(wB1.w) };
                    #pragma unroll
                    for (int p = 0; p < 4; ++p)
                        #pragma unroll
                        for (int j = 0; j < 8; ++j)
                            acc[p][j] = fma2(ap[p], wd[j], acc[p][j]);
                }
            }
        }
        __syncthreads();
        // stash h row-major (upper 64 logical cols at physical offset 68)
        #pragma unroll
        for (int p = 0; p < 4; ++p) {
            float lo[8], hi[8];
            #pragma unroll
            for (int j = 0; j < 8; ++j) {
                float2 t = funpk(acc[p][j]);
                lo[j] = t.x; hi[j] = t.y;
            }
            int ra = n0 + 2 * p, rb = ra + 1;
            *(float4*)&xbuf[ra * HSD + c0p]     = make_float4(lo[0], lo[1], lo[2], lo[3]);
            *(float4*)&xbuf[ra * HSD + c0p + 4] = make_float4(lo[4], lo[5], lo[6], lo[7]);
            *(float4*)&xbuf[rb * HSD + c0p]     = make_float4(hi[0], hi[1], hi[2], hi[3]);
            *(float4*)&xbuf[rb * HSD + c0p + 4] = make_float4(hi[4], hi[5], hi[6], hi[7]);
        }
        __syncthreads();

        // prefetch during agg: next layer's W/bias, or (layer 2) the head weights+biases
        if (layer < 2) {
            const float* Wn = (layer == 0) ? W1 : W2;
            const float* bn = (layer == 0) ? b1 : b2;
            float* bdst = (layer == 0) ? x3 : bsh;
            for (int i = tid * 4; i < HID * HID; i += NTHR * 4)
                cpa16(&Wsh[i], &Wn[i]);
            if (tid < 32) cpa16(&bdst[tid * 4], &bn[tid * 4]);
            CPA_COMMIT();
        } else {
            // c1w rows are 385 floats (4B-aligned only) -> scalar cp.async into padded rows
            for (int i = tid; i < 16 * TLD; i += NTHR) {
                int oc = i / TLD, t = i - oc * TLD;
                cpa4(&Wsh[oc * TLDP + t], &c1w[i]);
            }
            float* c2wsh = Wsh + 16 * TLDP;
            for (int i = tid * 4; i < 32 * 16 * 5; i += NTHR * 4)
                cpa16(&c2wsh[i], &c2w[i]);
            if (tid < 4) cpa16(&Wsh[HB_C1B + tid * 4], &c1b[tid * 4]);
            if (tid >= 4 && tid < 12) cpa16(&Wsh[HB_C2B + (tid - 4) * 4], &c2b[(tid - 4) * 4]);
            CPA_COMMIT();
        }

        // aggregation (segment_sum semantics): edges e-order (mul,add), self LAST, +bias, tanh
        // thread slot -> node via degree-balanced nodemap; (s,w) prefetched (branchless clamp)
        u64 r2[32];
        {
            const int node = nodemap[tid >> 1];
            #pragma unroll
            for (int q = 0; q < 32; ++q) r2[q] = 0ULL;
            int s0 = (node == 0) ? 0 : row_end[node - 1];
            int s1 = row_end[node];
            int s_cur = 0; float w_cur = 0.0f;
            if (s0 < s1) { s_cur = csrs[s0]; w_cur = csrn[s0]; }
            for (int ii = s0; ii < s1; ++ii) {
                int nxt = (ii + 1 < s1) ? (ii + 1) : ii;   // branchless clamp
                int s_nxt = csrs[nxt];
                float w_nxt = csrn[nxt];
                u64 wd = f2dup(w_cur);
                const u64x2* sp = (const u64x2*)&xbuf[s_cur * HSD + chp];
                #pragma unroll
                for (int q = 0; q < 16; ++q) {
                    u64x2 v = sp[q];
                    r2[2 * q]     = add2(r2[2 * q],     mul2(v.x, wd));
                    r2[2 * q + 1] = add2(r2[2 * q + 1], mul2(v.y, wd));
                }
                s_cur = s_nxt; w_cur = w_nxt;
            }
            u64 snd = f2dup(__fmul_rn(dinv[node], dinv[node]));
            const u64x2* hp = (const u64x2*)&xbuf[node * HSD + chp];
            #pragma unroll
            for (int q = 0; q < 16; ++q) {
                u64x2 v = hp[q];
                r2[2 * q]     = add2(r2[2 * q],     mul2(v.x, snd));
                r2[2 * q + 1] = add2(r2[2 * q + 1], mul2(v.y, snd));
            }
            #pragma unroll
            for (int q = 0; q < 32; ++q) {
                float2 t = funpk(r2[q]);
                t.x = xla_tanh(__fadd_rn(t.x, bcur[ch + 2 * q]));
                t.y = xla_tanh(__fadd_rn(t.y, bcur[ch + 2 * q + 1]));
                r2[q] = fpack(t.x, t.y);
            }
            float* xr = &xcat[(size_t)node * TLDP + layer * HID + ch];
            #pragma unroll
            for (int q = 0; q < 32; q += 2) {
                u64x2 v; v.x = r2[q]; v.y = r2[q + 1];
                *(u64x2*)&xr[2 * q] = v;
            }
            __syncthreads();
            // x^T writeback: rows ch+2q (ch=64 half at +4 col offset)
            #pragma unroll
            for (int q = 0; q < 32; ++q) {
                float2 t = funpk(r2[q]);
                xbuf[(ch + 2 * q) * XS + chx + node]     = t.x;
                xbuf[(ch + 2 * q + 1) * XS + chx + node] = t.y;
            }
        }
        if (layer < 2) CPA_WAIT();
        __syncthreads();
    }

    // ---------------- layer 3 : 128 -> 1 ----------------
    // XLA:CPU kTiledLlvmIrGemv semantics: 4-lane accumulators (lane = k mod 4,
    // ascending chunks, fused FMA), then shuffle-halving reduce (a0+a2)+(a1+a3).
    if (tid < HID) bsh[tid] = W3[tid];
    __syncthreads();
    float* h3 = (float*)cursor;
    if (tid < NPG) {
        float a0 = 0.0f, a1 = 0.0f, a2 = 0.0f, a3 = 0.0f;
        for (int m = 0; m < 64; m += 4) {
            a0 = __fmaf_rn(xbuf[(m + 0) * XS + tid], bsh[m + 0], a0);
            a1 = __fmaf_rn(xbuf[(m + 1) * XS + tid], bsh[m + 1], a1);
            a2 = __fmaf_rn(xbuf[(m + 2) * XS + tid], bsh[m + 2], a2);
            a3 = __fmaf_rn(xbuf[(m + 3) * XS + tid], bsh[m + 3], a3);
        }
        for (int m = 64; m < HID; m += 4) {
            a0 = __fmaf_rn(xbuf[(m + 0) * XS + 4 + tid], bsh[m + 0], a0);
            a1 = __fmaf_rn(xbuf[(m + 1) * XS + 4 + tid], bsh[m + 1], a1);
            a2 = __fmaf_rn(xbuf[(m + 2) * XS + 4 + tid], bsh[m + 2], a2);
            a3 = __fmaf_rn(xbuf[(m + 3) * XS + 4 + tid], bsh[m + 3], a3);
        }
        h3[tid] = __fadd_rn(__fadd_rn(a0, a2), __fadd_rn(a1, a3));
    }
    __syncthreads();
    if (tid < NPG) {
        float acc = 0.0f;
        int s0 = (tid == 0) ? 0 : row_end[tid - 1];
        int s1 = row_end[tid];
        for (int ii = s0; ii < s1; ++ii)
            acc = __fadd_rn(acc, __fmul_rn(h3[csrs[ii]], csrn[ii]));
        acc = __fadd_rn(acc, __fmul_rn(h3[tid], __fmul_rn(dinv[tid], dinv[tid])));
        acc = __fadd_rn(acc, b3[0]);
        float v = xla_tanh(acc);
        x3[tid] = v;
        xcat[(size_t)tid * TLDP + 384] = v;
    }
    __syncthreads();

    // ---------------- stable descending top-K via rank (2 threads/node, shfl combine) ----
    {
        int node = tid >> 1, ht = tid & 1;
        float v = x3[node];
        int part = 0;
        for (int j = ht * 128; j < ht * 128 + 128; ++j) {
            float u = x3[j];
            part += (u > v) || (u == v && j < node);
        }
        part += __shfl_xor_sync(0xffffffffu, part, 1);
        if (ht == 0 && part < KSEL) sel[part] = node;
    }
    __syncthreads();

    // ---------------- head (weights already cp.async'd during layer-2 agg) ----------------
    for (int idx = tid; idx < KSEL * TLDP; idx += NTHR) {
        int k = idx / TLDP, t = idx - k * TLDP;
        xbuf[idx] = (t < TLD) ? xcat[(size_t)sel[k] * TLDP + t] : 0.0f;
    }
    float* c2wsh = Wsh + 16 * TLDP;
    CPA_WAIT();          // head weights + biases landed
    __syncthreads();

    float* out1 = csrn;          // [16][60]
    float* pl   = csrn + 960;    // [16][30]
    float* v2   = csrn + 1440;   // [832]
    float* y1   = csrn + 2272;   // [128]
    float* part = csrn + 2400;   // [512]

    for (int task = tid; task < 16 * KSEL; task += NTHR) {
        int oc = task / KSEL, k = task - oc * KSEL;
        const float* pr = &xbuf[k * TLDP];
        const float* wr = &Wsh[oc * TLDP];
        float acc = Wsh[HB_C1B + oc];
        for (int t = 0; t < 384; t += 4) {
            float4 pv = *(const float4*)&pr[t];
            float4 wv = *(const float4*)&wr[t];
            acc += pv.x * wv.x + pv.y * wv.y + pv.z * wv.z + pv.w * wv.w;
        }
        acc += pr[384] * wr[384];
        out1[oc * KSEL + k] = fmaxf(acc, 0.0f);
    }
    __syncthreads();
    for (int task = tid; task < 16 * 30; task += NTHR) {
        int ic = task / 30, j = task - ic * 30;
        pl[ic * 30 + j] = fmaxf(out1[ic * 60 + 2 * j], out1[ic * 60 + 2 * j + 1]);
    }
    __syncthreads();
    for (int task = tid; task < 32 * 26; task += NTHR) {
        int oc = task / 26, j = task - oc * 26;
        float acc = Wsh[HB_C2B + oc];
        #pragma unroll
        for (int ic = 0; ic < 16; ++ic)
            #pragma unroll
            for (int p = 0; p < 5; ++p)
                acc += c2wsh[oc * 80 + ic * 5 + p] * pl[ic * 30 + j + p];
        v2[oc * 26 + j] = fmaxf(acc, 0.0f);
    }
    __syncthreads();
    {
        int o = tid & 127, pt = tid >> 7;
        float acc = 0.0f;
        for (int i = pt * 208; i < pt * 208 + 208; ++i)
            acc += v2[i] * l1w[i * HID + o];
        part[tid] = acc;
    }
    __syncthreads();
    if (tid < HID) {
        float y = part[tid] + part[tid + 128] + part[tid + 256] + part[tid + 384] + l1b[tid];
        y1[tid] = fmaxf(y, 0.0f);
    }
    __syncthreads();
    if (tid < HID) part[tid] = y1[tid] * l2w[tid];
    __syncthreads();
    if (tid == 0) {
        float s = 0.0f;
        for (int i = 0; i < HID; ++i) s += part[i];
        out[g] = s + l2b[0];
    }
}

extern "C" void kernel_launch(void* const* d_in, const int* in_sizes, int n_in,
                              void* d_out, int out_size) {
    (void)in_sizes; (void)n_in; (void)out_size;
    cudaFuncSetAttribute(dgcnn_fused, cudaFuncAttributeMaxDynamicSharedMemorySize, SMEM_BYTES);
    dgcnn_fused<<<NB, NTHR, SMEM_BYTES>>>(
        (const float*)d_in[0],  (const float*)d_in[1],  (const float*)d_in[2],
        (const float*)d_in[3],  (const float*)d_in[4],  (const float*)d_in[5],
        (const float*)d_in[6],  (const float*)d_in[7],  (const float*)d_in[8],
        (const float*)d_in[9],  (const float*)d_in[10], (const float*)d_in[11],
        (const float*)d_in[12], (const float*)d_in[13], (const float*)d_in[14],
        (const float*)d_in[15], (const float*)d_in[16], (const float*)d_in[17],
        (const int*)d_in[18],   (const int*)d_in[19],
        (float*)d_out);
}